// round 4
// baseline (speedup 1.0000x reference)
#include <cuda_runtime.h>

#define DD 11
#define NTOK 49
#define SEQ 900
#define FFD 64

__global__ __launch_bounds__(256) void pve_kernel(
    const float* __restrict__ x,     // [10,16,16]
    const float* __restrict__ Wqkv,  // [33,11]
    const float* __restrict__ Wo,    // [11,11]
    const float* __restrict__ W1,    // [64,11]
    const float* __restrict__ W2,    // [11,64]
    const float* __restrict__ ln1,   // [11]
    const float* __restrict__ ln2,   // [11]
    float* __restrict__ out)         // [256,10,900]
{
    __shared__ float sWqkv[363];
    __shared__ float sWo[121];
    __shared__ float sW1[704];
    __shared__ float sW2[704];
    __shared__ float sln1[DD], sln2[DD];
    __shared__ float sK[NTOK * DD];
    __shared__ float sV[NTOK * DD];
    __shared__ float sOut[50 * DD];

    const int tid = threadIdx.x;
    const int nthr = blockDim.x;

    for (int i = tid; i < 363; i += nthr) sWqkv[i] = Wqkv[i];
    for (int i = tid; i < 121; i += nthr) sWo[i]   = Wo[i];
    for (int i = tid; i < 704; i += nthr) sW1[i]   = W1[i];
    for (int i = tid; i < 704; i += nthr) sW2[i]   = W2[i];
    if (tid < DD) { sln1[tid] = ln1[tid]; sln2[tid] = ln2[tid]; }

    const int b  = blockIdx.x;
    const int ph = b >> 4;
    const int pw = b & 15;

    // ---- gather token input vector (registers) ----
    float xv[DD];
    if (tid < 50) {
        if (tid < NTOK) {
            const int i = tid / 7, j = tid % 7;
            const int hh = ph + i - 3, ww = pw + j - 3;
            const bool inb = ((unsigned)hh < 16u) && ((unsigned)ww < 16u);
            #pragma unroll
            for (int c = 0; c < 10; c++)
                xv[c] = inb ? x[c * 256 + hh * 16 + ww] : 0.f;
            xv[10] = inb ? 0.f : 1.f;   // mask channel: 1 in padded border
        } else {
            #pragma unroll
            for (int c = 0; c < DD; c++) xv[c] = 0.f;
        }
    }
    __syncthreads();   // weights staged

    // ---- qkv projection; stage k,v for the 49 real tokens ----
    float q[DD];
    if (tid < 50) {
        #pragma unroll
        for (int d = 0; d < DD; d++) {
            float aq = 0.f, ak = 0.f, av = 0.f;
            #pragma unroll
            for (int e = 0; e < DD; e++) {
                const float xe = xv[e];
                aq += sWqkv[d * DD + e]            * xe;
                ak += sWqkv[(DD + d) * DD + e]     * xe;
                av += sWqkv[(2 * DD + d) * DD + e] * xe;
            }
            q[d] = aq;
            if (tid < NTOK) { sK[tid * DD + d] = ak; sV[tid * DD + d] = av; }
        }
    }
    __syncthreads();

    if (tid < 50) {
        // ---- attention over 49 real keys + 851 implicit zero keys ----
        const float scale = rsqrtf(11.f);
        float Z = 851.f;                 // 851 zero keys contribute exp(0)=1 each
        float sa[DD];
        #pragma unroll
        for (int d = 0; d < DD; d++) sa[d] = 0.f;
        for (int u = 0; u < NTOK; u++) {
            float s = 0.f;
            #pragma unroll
            for (int d = 0; d < DD; d++) s += q[d] * sK[u * DD + d];
            const float e = __expf(s * scale);
            Z += e;
            #pragma unroll
            for (int d = 0; d < DD; d++) sa[d] += e * sV[u * DD + d];
        }
        const float invZ = 1.f / Z;

        // ---- out proj + residual + layernorm1 ----
        float r[DD];
        #pragma unroll
        for (int d = 0; d < DD; d++) {
            float a = 0.f;
            #pragma unroll
            for (int e = 0; e < DD; e++) a += sWo[d * DD + e] * sa[e];
            r[d] = xv[d] + a * invZ;
        }
        float mean = 0.f;
        #pragma unroll
        for (int d = 0; d < DD; d++) mean += r[d];
        mean *= (1.f / 11.f);
        float var = 0.f;
        #pragma unroll
        for (int d = 0; d < DD; d++) { const float t = r[d] - mean; var += t * t; }
        var *= (1.f / 11.f);
        float rstd = rsqrtf(var + 1e-5f);
        float x1[DD];
        #pragma unroll
        for (int d = 0; d < DD; d++) x1[d] = (r[d] - mean) * rstd * sln1[d];

        // ---- feedforward ----
        float y[DD];
        #pragma unroll
        for (int d = 0; d < DD; d++) y[d] = x1[d];   // residual preloaded
        for (int f = 0; f < FFD; f++) {
            float h = 0.f;
            #pragma unroll
            for (int d = 0; d < DD; d++) h += sW1[f * DD + d] * x1[d];
            h = fmaxf(h, 0.f);
            #pragma unroll
            for (int d = 0; d < DD; d++) y[d] += sW2[d * FFD + f] * h;
        }

        // ---- layernorm2 -> shared ----
        mean = 0.f;
        #pragma unroll
        for (int d = 0; d < DD; d++) mean += y[d];
        mean *= (1.f / 11.f);
        var = 0.f;
        #pragma unroll
        for (int d = 0; d < DD; d++) { const float t = y[d] - mean; var += t * t; }
        var *= (1.f / 11.f);
        rstd = rsqrtf(var + 1e-5f);
        #pragma unroll
        for (int d = 0; d < DD; d++)
            sOut[tid * DD + d] = (y[d] - mean) * rstd * sln2[d];
    }
    __syncthreads();

    // ---- scatter to output: out[b, c, s], s = i*30+j; window at i<7 && j<7 ----
    float* ob = out + b * (10 * SEQ);
    for (int idx = tid; idx < 10 * SEQ; idx += nthr) {
        const int c = idx / SEQ;
        const int s = idx - c * SEQ;
        const int i = s / 30;
        const int j = s - i * 30;
        const int tok = (i < 7 && j < 7) ? (i * 7 + j) : NTOK;
        ob[idx] = sOut[tok * DD + c];
    }
}

extern "C" void kernel_launch(void* const* d_in, const int* in_sizes, int n_in,
                              void* d_out, int out_size) {
    const float* x    = (const float*)d_in[0];
    const float* Wqkv = (const float*)d_in[1];
    const float* Wo   = (const float*)d_in[2];
    const float* W1   = (const float*)d_in[3];
    const float* W2   = (const float*)d_in[4];
    const float* ln1  = (const float*)d_in[5];
    const float* ln2  = (const float*)d_in[6];
    float* out = (float*)d_out;
    pve_kernel<<<256, 256>>>(x, Wqkv, Wo, W1, W2, ln1, ln2, out);
}